// round 2
// baseline (speedup 1.0000x reference)
#include <cuda_runtime.h>

#define BATCH 512
#define NCOL 4096
#define TPB 256
#define EPB (NCOL / TPB)   // 16 elements per thread
#define EPSI 0.1f
#define MAX_ITER 200
#define PADC 1e-16f
#define NU0 (256.0f / 4096.0f)    // K/N
#define NU1 (3840.0f / 4096.0f)   // (N-K)/N
#define MUC (1.0f / 4096.0f)

__device__ int g_max_bits;

__global__ void init_max_kernel() {
    g_max_bits = 0;
}

__global__ void max_kernel(const float* __restrict__ s) {
    int idx = blockIdx.x * blockDim.x + threadIdx.x;
    int stride = gridDim.x * blockDim.x;
    float m = 0.0f;
    for (int i = idx; i < BATCH * NCOL; i += stride) {
        float x = s[i];
        float x1 = x - 1.0f;
        m = fmaxf(m, fmaxf(x * x, x1 * x1));
    }
#pragma unroll
    for (int o = 16; o; o >>= 1)
        m = fmaxf(m, __shfl_xor_sync(0xffffffffu, m, o));
    __shared__ float sm[8];
    int lane = threadIdx.x & 31, w = threadIdx.x >> 5;
    if (lane == 0) sm[w] = m;
    __syncthreads();
    if (w == 0) {
        m = (lane < (int)(blockDim.x >> 5)) ? sm[lane] : 0.0f;
#pragma unroll
        for (int o = 4; o; o >>= 1)
            m = fmaxf(m, __shfl_xor_sync(0xffffffffu, m, o));
        if (lane == 0)
            atomicMax(&g_max_bits, __float_as_int(m));  // m >= 0: int compare valid
    }
}

__global__ __launch_bounds__(TPB, 4)
void sinkhorn_kernel(const float* __restrict__ s, float* __restrict__ out) {
    const int b = blockIdx.x;
    const int t = threadIdx.x;
    const int lane = t & 31, w = t >> 5;

    const float Cmax = __int_as_float(g_max_bits);
    const float ainv = __fdividef(1.0f, Cmax * EPSI);  // exponent scale: C/Cmax/eps

    float G0[EPB], G1[EPB];
    float a0 = 0.0f, a1 = 0.0f;
    const float* __restrict__ row = s + (size_t)b * NCOL;
#pragma unroll
    for (int j = 0; j < EPB; j++) {
        float x = row[t + j * TPB];
        float x1 = x - 1.0f;
        float g0 = __expf(-x * x * ainv);
        float g1 = __expf(-x1 * x1 * ainv);
        G0[j] = g0;
        G1[j] = g1;
        a0 += g0;     // S with v = 1 (initial v0 = ones)
        a1 += g1;
    }

    __shared__ float p0[2][8], p1[2][8];
    int buf = 0;
    float S0, S1;

    // --- initial reduction: S_k = sum_n G_k (v = 1) ---
#pragma unroll
    for (int o = 16; o; o >>= 1) {
        a0 += __shfl_xor_sync(0xffffffffu, a0, o);
        a1 += __shfl_xor_sync(0xffffffffu, a1, o);
    }
    if (lane == 0) { p0[buf][w] = a0; p1[buf][w] = a1; }
    __syncthreads();
    S0 = 0.0f; S1 = 0.0f;
#pragma unroll
    for (int i = 0; i < 8; i++) { S0 += p0[buf][i]; S1 += p1[buf][i]; }
    buf ^= 1;

    float u0 = 1.0f, u1 = 1.0f;

    // --- 200 Sinkhorn iterations, 1 barrier per iteration (double-buffered) ---
    for (int it = 0; it < MAX_ITER; ++it) {
        u0 = __fdividef(NU0, S0 + PADC);
        u1 = __fdividef(NU1, S1 + PADC);
        a0 = 0.0f; a1 = 0.0f;
#pragma unroll
        for (int j = 0; j < EPB; j++) {
            float d = fmaf(u0, G0[j], fmaf(u1, G1[j], PADC));
            float v = __fdividef(MUC, d);
            a0 = fmaf(G0[j], v, a0);
            a1 = fmaf(G1[j], v, a1);
        }
#pragma unroll
        for (int o = 16; o; o >>= 1) {
            a0 += __shfl_xor_sync(0xffffffffu, a0, o);
            a1 += __shfl_xor_sync(0xffffffffu, a1, o);
        }
        if (lane == 0) { p0[buf][w] = a0; p1[buf][w] = a1; }
        __syncthreads();
        S0 = 0.0f; S1 = 0.0f;
#pragma unroll
        for (int i = 0; i < 8; i++) { S0 += p0[buf][i]; S1 += p1[buf][i]; }
        buf ^= 1;
    }

    // u0,u1 now hold u_200; recompute v_200 per element and write P = u * G * v
    float* __restrict__ o0 = out + (size_t)b * 2 * NCOL;
    float* __restrict__ o1 = o0 + NCOL;
#pragma unroll
    for (int j = 0; j < EPB; j++) {
        float d = fmaf(u0, G0[j], fmaf(u1, G1[j], PADC));
        float v = __fdividef(MUC, d);
        o0[t + j * TPB] = u0 * G0[j] * v;
        o1[t + j * TPB] = u1 * G1[j] * v;
    }
}

extern "C" void kernel_launch(void* const* d_in, const int* in_sizes, int n_in,
                              void* d_out, int out_size) {
    const float* scores = (const float*)d_in[0];
    float* out = (float*)d_out;

    init_max_kernel<<<1, 1>>>();
    max_kernel<<<256, 256>>>(scores);
    sinkhorn_kernel<<<BATCH, TPB>>>(scores, out);
}

// round 3
// speedup vs baseline: 1.6092x; 1.6092x over previous
#include <cuda_runtime.h>

#define BATCH 512
#define NCOL 4096
#define TPB 256
#define EPB (NCOL / TPB)   // 16 elements per thread
#define NPAIR (EPB / 2)    // 8 pairs per thread
#define EPSI 0.1f
#define MAX_ITER 200
#define PADC 1e-16f
#define MUC (1.0f / 4096.0f)
#define NU_RATIO 15.0f     // NU1/NU0 = (N-K)/K

__device__ int g_max_bits;

__global__ void init_max_kernel() {
    g_max_bits = 0;
}

__global__ void max_kernel(const float* __restrict__ s) {
    int idx = blockIdx.x * blockDim.x + threadIdx.x;
    int stride = gridDim.x * blockDim.x;
    float m = 0.0f;
    for (int i = idx; i < BATCH * NCOL; i += stride) {
        float x = s[i];
        float x1 = x - 1.0f;
        m = fmaxf(m, fmaxf(x * x, x1 * x1));
    }
#pragma unroll
    for (int o = 16; o; o >>= 1)
        m = fmaxf(m, __shfl_xor_sync(0xffffffffu, m, o));
    __shared__ float sm[8];
    int lane = threadIdx.x & 31, w = threadIdx.x >> 5;
    if (lane == 0) sm[w] = m;
    __syncthreads();
    if (w == 0) {
        m = (lane < (int)(blockDim.x >> 5)) ? sm[lane] : 0.0f;
#pragma unroll
        for (int o = 4; o; o >>= 1)
            m = fmaxf(m, __shfl_xor_sync(0xffffffffu, m, o));
        if (lane == 0)
            atomicMax(&g_max_bits, __float_as_int(m));  // m >= 0: int compare valid
    }
}

__device__ __forceinline__ float rcp_fast(float x) {
    float r;
    asm("rcp.approx.f32 %0, %1;" : "=f"(r) : "f"(x));
    return r;
}

__global__ __launch_bounds__(TPB, 4)
void sinkhorn_kernel(const float* __restrict__ s, float* __restrict__ out) {
    const int b = blockIdx.x;
    const int t = threadIdx.x;
    const int lane = t & 31, w = t >> 5;

    const float Cmax = __int_as_float(g_max_bits);
    const float ainv = rcp_fast(Cmax * EPSI);   // exponent scale: 1/(Cmax*eps)

    // ---- load row, build q[n] = G1/G0 = exp((2x-1)*ainv), and initial sums ----
    const float* __restrict__ row = s + (size_t)b * NCOL;
    float q[EPB];
    float s0 = 0.0f, s1 = 0.0f;
#pragma unroll
    for (int j = 0; j < EPB; j++) {
        float x = row[t + j * TPB];
        float x1 = x - 1.0f;
        s0 += __expf(-x * x * ainv);
        s1 += __expf(-x1 * x1 * ainv);
        q[j] = __expf((2.0f * x - 1.0f) * ainv);
    }
    // pair coefficients: 1/(1+r qa) + 1/(1+r qb) = (2 + r*sq)/(1 + r*sq + r^2*pq)
    float sq[NPAIR], pq[NPAIR];
#pragma unroll
    for (int j = 0; j < NPAIR; j++) {
        sq[j] = q[j] + q[j + NPAIR];
        pq[j] = q[j] * q[j + NPAIR];
    }

    // ---- initial block reduction of s0, s1 (iteration 1: v = ones) ----
    __shared__ float2 ired[8];
    __shared__ float p[2][8];
#pragma unroll
    for (int o = 16; o; o >>= 1) {
        s0 += __shfl_xor_sync(0xffffffffu, s0, o);
        s1 += __shfl_xor_sync(0xffffffffu, s1, o);
    }
    if (lane == 0) ired[w] = make_float2(s0, s1);
    __syncthreads();
    float S0 = 0.0f, S1 = 0.0f;
#pragma unroll
    for (int i = 0; i < 8; i++) { S0 += ired[i].x; S1 += ired[i].y; }

    // r_1 = u1/u0 after first u-update (v0 = ones)
    float r = NU_RATIO * (S0 + PADC) * rcp_fast(S1 + PADC);

    // ---- 199 remaining iterations: 1D map on r ----
    int buf = 0;
    for (int it = 1; it < MAX_ITER; ++it) {
        float r2 = r * r;
        float A0 = 0.0f, A1 = 0.0f;
#pragma unroll
        for (int j = 0; j < NPAIR; j++) {
            float c = fmaf(r, sq[j], 1.0f);        // 1 + r*sq
            float den = fmaf(r2, pq[j], c);        // 1 + r*sq + r^2*pq
            float num = c + 1.0f;                  // 2 + r*sq
            float rc = rcp_fast(den);
            if (j & 1) A1 = fmaf(num, rc, A1);
            else       A0 = fmaf(num, rc, A0);
        }
        float a = A0 + A1;
#pragma unroll
        for (int o = 16; o; o >>= 1)
            a += __shfl_xor_sync(0xffffffffu, a, o);
        if (lane == 0) p[buf][w] = a;
        __syncthreads();
        float A = 0.0f;
#pragma unroll
        for (int i = 0; i < 8; i++) A += p[buf][i];
        buf ^= 1;

        float B = MUC * A;                         // = u0*S0'
        r = NU_RATIO * r * B * rcp_fast(1.0f - B); // r' = r*(nu1/nu0)*B/(1-B)
    }

    // ---- output: P0 = MUC/(1+r*q), P1 = MUC - P0 ----
    float* __restrict__ o0 = out + (size_t)b * 2 * NCOL;
    float* __restrict__ o1 = o0 + NCOL;
#pragma unroll
    for (int j = 0; j < EPB; j++) {
        float x = row[t + j * TPB];
        float qq = __expf((2.0f * x - 1.0f) * ainv);
        float p0 = MUC * rcp_fast(fmaf(r, qq, 1.0f));
        o0[t + j * TPB] = p0;
        o1[t + j * TPB] = MUC - p0;
    }
}

extern "C" void kernel_launch(void* const* d_in, const int* in_sizes, int n_in,
                              void* d_out, int out_size) {
    const float* scores = (const float*)d_in[0];
    float* out = (float*)d_out;

    init_max_kernel<<<1, 1>>>();
    max_kernel<<<256, 256>>>(scores);
    sinkhorn_kernel<<<BATCH, TPB>>>(scores, out);
}

// round 4
// speedup vs baseline: 10.3462x; 6.4294x over previous
#include <cuda_runtime.h>

#define BATCH 512
#define NCOL 4096
#define TPB 256
#define EPB (NCOL / TPB)   // 16 elements per thread
#define EPSI 0.1f
#define KTOP 256.0f
#define MUC (1.0f / 4096.0f)
#define NMAXBLK 256
#define MAX_NEWTON 40

__device__ float g_partials[NMAXBLK];   // per-block maxes; fully rewritten every launch

__device__ __forceinline__ float rcp_fast(float x) {
    float r;
    asm("rcp.approx.f32 %0, %1;" : "=f"(r) : "f"(x));
    return r;
}

__global__ void max_kernel(const float* __restrict__ s) {
    int idx = blockIdx.x * blockDim.x + threadIdx.x;
    int stride = gridDim.x * blockDim.x;
    float m = 0.0f;
    for (int i = idx; i < BATCH * NCOL; i += stride) {
        float x = s[i];
        float x1 = x - 1.0f;
        m = fmaxf(m, fmaxf(x * x, x1 * x1));
    }
#pragma unroll
    for (int o = 16; o; o >>= 1)
        m = fmaxf(m, __shfl_xor_sync(0xffffffffu, m, o));
    __shared__ float sm[8];
    int lane = threadIdx.x & 31, w = threadIdx.x >> 5;
    if (lane == 0) sm[w] = m;
    __syncthreads();
    if (threadIdx.x == 0) {
#pragma unroll
        for (int i = 1; i < 8; i++) m = fmaxf(m, sm[i]);
        g_partials[blockIdx.x] = m;
    }
}

__global__ __launch_bounds__(TPB, 4)
void sinkhorn_kernel(const float* __restrict__ s, float* __restrict__ out) {
    const int b = blockIdx.x;
    const int t = threadIdx.x;
    const int lane = t & 31, w = t >> 5;

    __shared__ float smax[8];
    __shared__ float2 p[2][8];

    // ---- global Cmax from per-block partials (TPB == NMAXBLK) ----
    float m = g_partials[t];
#pragma unroll
    for (int o = 16; o; o >>= 1)
        m = fmaxf(m, __shfl_xor_sync(0xffffffffu, m, o));
    if (lane == 0) smax[w] = m;
    __syncthreads();
    float Cmax = smax[0];
#pragma unroll
    for (int i = 1; i < 8; i++) Cmax = fmaxf(Cmax, smax[i]);

    const float ainv = rcp_fast(Cmax * EPSI);   // 1/(Cmax*eps)

    // ---- load row, build q[n] = G1/G0 = exp((2x-1)*ainv) ----
    const float* __restrict__ row = s + (size_t)b * NCOL;
    float q[EPB];
#pragma unroll
    for (int j = 0; j < EPB; j++) {
        float x = row[t + j * TPB];
        q[j] = __expf((2.0f * x - 1.0f) * ainv);
    }

    // ---- safeguarded Newton in theta = ln r on  h = sum 1/(1+r*q) - K = 0 ----
    float r = 1.0f;
    int buf = 0;
    for (int it = 0; it < MAX_NEWTON; ++it) {
        float A = 0.0f, A2 = 0.0f;
#pragma unroll
        for (int j = 0; j < EPB; j++) {
            float rc = rcp_fast(fmaf(r, q[j], 1.0f));
            A += rc;
            A2 = fmaf(rc, rc, A2);
        }
#pragma unroll
        for (int o = 16; o; o >>= 1) {
            A  += __shfl_xor_sync(0xffffffffu, A, o);
            A2 += __shfl_xor_sync(0xffffffffu, A2, o);
        }
        if (lane == 0) p[buf][w] = make_float2(A, A2);
        __syncthreads();
        float sA = 0.0f, sA2 = 0.0f;
#pragma unroll
        for (int i = 0; i < 8; i++) { sA += p[buf][i].x; sA2 += p[buf][i].y; }
        buf ^= 1;

        // dh/dtheta = -(A - A2);  theta step = (A - K)/(A - A2), clamped
        float denom = fmaxf(sA - sA2, 1e-30f);
        float step = __fdividef(sA - KTOP, denom);
        step = fminf(fmaxf(step, -4.0f), 4.0f);
        r *= __expf(step);                        // uniform across block
        if (fabsf(step) < 1e-6f) break;           // uniform branch
    }

    // ---- output: P0 = MUC/(1+r*q), P1 = MUC - P0 ----
    float* __restrict__ o0 = out + (size_t)b * 2 * NCOL;
    float* __restrict__ o1 = o0 + NCOL;
#pragma unroll
    for (int j = 0; j < EPB; j++) {
        float p0 = MUC * rcp_fast(fmaf(r, q[j], 1.0f));
        o0[t + j * TPB] = p0;
        o1[t + j * TPB] = MUC - p0;
    }
}

extern "C" void kernel_launch(void* const* d_in, const int* in_sizes, int n_in,
                              void* d_out, int out_size) {
    const float* scores = (const float*)d_in[0];
    float* out = (float*)d_out;

    max_kernel<<<NMAXBLK, 256>>>(scores);
    sinkhorn_kernel<<<BATCH, TPB>>>(scores, out);
}

// round 5
// speedup vs baseline: 12.4339x; 1.2018x over previous
#include <cuda_runtime.h>

#define BATCH 512
#define NCOL 4096
#define TPB 256
#define EPB (NCOL / TPB)   // 16 elements per thread
#define EPSI 0.1f
#define KTOP 256.0f
#define MUC (1.0f / 4096.0f)
#define MAX_HALLEY 24

__device__ float g_partials[BATCH];     // per-row maxes; fully rewritten every launch
__device__ unsigned g_count;            // monotone arrival counter (replay-safe)

__device__ __forceinline__ float rcp_fast(float x) {
    float r;
    asm("rcp.approx.f32 %0, %1;" : "=f"(r) : "f"(x));
    return r;
}

__device__ __forceinline__ float ldcg_f(const float* p) {
    float v;
    asm volatile("ld.global.cg.f32 %0, [%1];" : "=f"(v) : "l"(p));
    return v;
}

__device__ __forceinline__ void stcs_f(float* p, float v) {
    asm volatile("st.global.cs.f32 [%0], %1;" :: "l"(p), "f"(v));
}

__global__ __launch_bounds__(TPB, 4)
void fused_kernel(const float* __restrict__ s, float* __restrict__ out) {
    const int b = blockIdx.x;
    const int t = threadIdx.x;
    const int lane = t & 31, w = t >> 5;

    __shared__ float smax[8];
    __shared__ float3 p3[2][8];

    // ---- load row into registers, local max of max(x^2, (x-1)^2) ----
    const float* __restrict__ row = s + (size_t)b * NCOL;
    float xq[EPB];
    float m = 0.0f;
#pragma unroll
    for (int j = 0; j < EPB; j++) {
        float x = row[t + j * TPB];
        xq[j] = x;
        float x1 = x - 1.0f;
        m = fmaxf(m, fmaxf(x * x, x1 * x1));
    }
#pragma unroll
    for (int o = 16; o; o >>= 1)
        m = fmaxf(m, __shfl_xor_sync(0xffffffffu, m, o));
    if (lane == 0) smax[w] = m;
    __syncthreads();

    // ---- publish partial, software grid barrier (all 512 blocks co-resident) ----
    if (t == 0) {
        float bm = smax[0];
#pragma unroll
        for (int i = 1; i < 8; i++) bm = fmaxf(bm, smax[i]);
        g_partials[b] = bm;
        __threadfence();                                   // release
        unsigned ticket = atomicAdd(&g_count, 1u);
        unsigned target = ((ticket >> 9) + 1u) << 9;       // next multiple of 512
        while (atomicAdd(&g_count, 0u) < target) { }       // spin (L2 atomic poll)
    }
    __syncthreads();

    // ---- global Cmax from the 512 partials (L2 reads, bypass L1) ----
    float gm = fmaxf(ldcg_f(&g_partials[t]), ldcg_f(&g_partials[t + 256]));
#pragma unroll
    for (int o = 16; o; o >>= 1)
        gm = fmaxf(gm, __shfl_xor_sync(0xffffffffu, gm, o));
    if (lane == 0) smax[w] = gm;
    __syncthreads();
    float Cmax = smax[0];
#pragma unroll
    for (int i = 1; i < 8; i++) Cmax = fmaxf(Cmax, smax[i]);

    const float ainv = rcp_fast(Cmax * EPSI);   // 1/(Cmax*eps)

    // ---- q[n] = G1/G0 = exp((2x-1)*ainv), in place over x ----
#pragma unroll
    for (int j = 0; j < EPB; j++)
        xq[j] = __expf((2.0f * xq[j] - 1.0f) * ainv);

    // ---- safeguarded Halley in theta = ln r on  h = sum 1/(1+r*q) - K = 0 ----
    float r = 1.0f;
    int buf = 0;
    for (int it = 0; it < MAX_HALLEY; ++it) {
        float A = 0.0f, A2 = 0.0f, A3 = 0.0f;
#pragma unroll
        for (int j = 0; j < EPB; j++) {
            float rc = rcp_fast(fmaf(r, xq[j], 1.0f));
            float rc2 = rc * rc;
            A += rc;
            A2 += rc2;
            A3 = fmaf(rc2, rc, A3);
        }
#pragma unroll
        for (int o = 16; o; o >>= 1) {
            A  += __shfl_xor_sync(0xffffffffu, A, o);
            A2 += __shfl_xor_sync(0xffffffffu, A2, o);
            A3 += __shfl_xor_sync(0xffffffffu, A3, o);
        }
        if (lane == 0) p3[buf][w] = make_float3(A, A2, A3);
        __syncthreads();
        float sA = 0.0f, sA2 = 0.0f, sA3 = 0.0f;
#pragma unroll
        for (int i = 0; i < 8; i++) {
            sA += p3[buf][i].x; sA2 += p3[buf][i].y; sA3 += p3[buf][i].z;
        }
        buf ^= 1;

        // h = A-K, h' = -(A-A2), h'' = A-3A2+2A3   (derivatives wrt theta = ln r)
        float h  = sA - KTOP;
        float h1 = -(sA - sA2);
        float h2 = sA - 3.0f * sA2 + 2.0f * sA3;
        float stepN = -h * rcp_fast(fminf(h1, -1e-30f));            // Newton (h1 < 0)
        float denH  = fmaf(-0.5f * h, h2, h1 * h1);
        float stepH = -h * h1 * rcp_fast(denH);
        float step = (denH > 1e-30f) ? stepH : stepN;               // uniform select
        if (!(step == step)) step = stepN;                          // NaN guard
        step = fminf(fmaxf(step, -4.0f), 4.0f);
        r *= __expf(step);                                          // uniform
        if (fabsf(step) < 1e-6f) break;                             // uniform branch
    }

    // ---- output: P0 = MUC/(1+r*q), P1 = MUC - P0, streaming stores ----
    float* __restrict__ o0 = out + (size_t)b * 2 * NCOL;
    float* __restrict__ o1 = o0 + NCOL;
#pragma unroll
    for (int j = 0; j < EPB; j++) {
        float p0 = MUC * rcp_fast(fmaf(r, xq[j], 1.0f));
        stcs_f(&o0[t + j * TPB], p0);
        stcs_f(&o1[t + j * TPB], MUC - p0);
    }
}

extern "C" void kernel_launch(void* const* d_in, const int* in_sizes, int n_in,
                              void* d_out, int out_size) {
    const float* scores = (const float*)d_in[0];
    float* out = (float*)d_out;
    fused_kernel<<<BATCH, TPB>>>(scores, out);
}

// round 7
// speedup vs baseline: 12.5459x; 1.0090x over previous
#include <cuda_runtime.h>

#define BATCH 512
#define NCOL 4096
#define TPB 256
#define EPB 16            // elements per thread (4 float4)
#define NV4 4             // float4 chunks per thread
#define EPSI 0.1f
#define KTOP 256.0f
#define MUC (1.0f / 4096.0f)
#define MAX_HALLEY 24

__device__ int g_max_bits;          // atomicMax target; idempotent across replays
__device__ unsigned g_count;        // monotone arrival counter (replay-safe)
__device__ unsigned g_release;      // monotone generation release counter

__device__ __forceinline__ float rcp_fast(float x) {
    float r;
    asm("rcp.approx.f32 %0, %1;" : "=f"(r) : "f"(x));
    return r;
}

__device__ __forceinline__ unsigned ldcg_u(const unsigned* p) {
    unsigned v;
    asm volatile("ld.global.cg.u32 %0, [%1];" : "=r"(v) : "l"(p));
    return v;
}

__device__ __forceinline__ int ldcg_i(const int* p) {
    int v;
    asm volatile("ld.global.cg.s32 %0, [%1];" : "=r"(v) : "l"(p));
    return v;
}

__device__ __forceinline__ void stcs_f4(float4* p, float4 v) {
    asm volatile("st.global.cs.v4.f32 [%0], {%1,%2,%3,%4};"
                 :: "l"(p), "f"(v.x), "f"(v.y), "f"(v.z), "f"(v.w));
}

__global__ __launch_bounds__(TPB, 4)
void fused_kernel(const float* __restrict__ s, float* __restrict__ out) {
    const int b = blockIdx.x;
    const int t = threadIdx.x;
    const int lane = t & 31, w = t >> 5;

    __shared__ float smax[8];
    __shared__ float3 p3[2][8];

    // ---- vectorized row load: thread t owns elements j*1024 + 4t .. +3 ----
    const float4* __restrict__ row4 = (const float4*)(s + (size_t)b * NCOL);
    float xq[EPB];
    float m = 0.0f;
#pragma unroll
    for (int j = 0; j < NV4; j++) {
        float4 v = row4[j * TPB + t];
        xq[j * 4 + 0] = v.x; xq[j * 4 + 1] = v.y;
        xq[j * 4 + 2] = v.z; xq[j * 4 + 3] = v.w;
    }
#pragma unroll
    for (int e = 0; e < EPB; e++) {
        float x = xq[e], x1 = x - 1.0f;
        m = fmaxf(m, fmaxf(x * x, x1 * x1));
    }
#pragma unroll
    for (int o = 16; o; o >>= 1)
        m = fmaxf(m, __shfl_xor_sync(0xffffffffu, m, o));
    if (lane == 0) smax[w] = m;
    __syncthreads();

    // ---- publish via atomicMax, then software grid barrier ----
    if (t == 0) {
        float bm = smax[0];
#pragma unroll
        for (int i = 1; i < 8; i++) bm = fmaxf(bm, smax[i]);
        atomicMax(&g_max_bits, __float_as_int(bm));   // bm >= 0: int compare valid
        __threadfence();                              // release max before ticket
        unsigned ticket = atomicAdd(&g_count, 1u);
        unsigned gen = ticket >> 9;                   // 512 blocks per generation
        if ((ticket & 511u) == 511u)
            atomicAdd(&g_release, 1u);                // last arriver releases
        else
            while (ldcg_u(&g_release) < gen + 1u) { }
        __threadfence();                              // acquire
    }
    __syncthreads();

    const float Cmax = __int_as_float(ldcg_i(&g_max_bits));
    const float ainv = rcp_fast(Cmax * EPSI);         // 1/(Cmax*eps)

    // ---- q[n] = G1/G0 = exp((2x-1)*ainv), in place ----
#pragma unroll
    for (int e = 0; e < EPB; e++)
        xq[e] = __expf((2.0f * xq[e] - 1.0f) * ainv);

    // ---- safeguarded Halley in theta = ln r on  h = sum 1/(1+r*q) - K = 0 ----
    float r = 1.0f;
    int buf = 0;
    for (int it = 0; it < MAX_HALLEY; ++it) {
        float A = 0.0f, A2 = 0.0f, A3 = 0.0f;
#pragma unroll
        for (int e = 0; e < EPB; e++) {
            float rc = rcp_fast(fmaf(r, xq[e], 1.0f));
            float rc2 = rc * rc;
            A += rc;
            A2 += rc2;
            A3 = fmaf(rc2, rc, A3);
        }
        // interleaved 3-value butterfly: the three chains pipeline per level
#pragma unroll
        for (int o = 16; o; o >>= 1) {
            A  += __shfl_xor_sync(0xffffffffu, A, o);
            A2 += __shfl_xor_sync(0xffffffffu, A2, o);
            A3 += __shfl_xor_sync(0xffffffffu, A3, o);
        }
        if (lane == 0) p3[buf][w] = make_float3(A, A2, A3);
        __syncthreads();
        float sA = 0.0f, sA2 = 0.0f, sA3 = 0.0f;
#pragma unroll
        for (int i = 0; i < 8; i++) {
            sA += p3[buf][i].x; sA2 += p3[buf][i].y; sA3 += p3[buf][i].z;
        }
        buf ^= 1;

        // h = A-K, h' = -(A-A2), h'' = A-3A2+2A3   (theta = ln r)
        float h  = sA - KTOP;
        float h1 = -(sA - sA2);
        float h2 = sA - 3.0f * sA2 + 2.0f * sA3;
        float stepN = -h * rcp_fast(fminf(h1, -1e-30f));
        float denH  = fmaf(-0.5f * h, h2, h1 * h1);
        float stepH = -h * h1 * rcp_fast(denH);
        float step = (denH > 1e-30f) ? stepH : stepN;
        if (!(step == step)) step = stepN;            // NaN guard
        step = fminf(fmaxf(step, -4.0f), 4.0f);
        r *= __expf(step);                            // uniform across block
        if (fabsf(step) < 1e-6f) break;               // uniform branch
    }

    // ---- output: P0 = MUC/(1+r*q), P1 = MUC - P0, vector streaming stores ----
    float4* __restrict__ o0 = (float4*)(out + (size_t)b * 2 * NCOL);
    float4* __restrict__ o1 = o0 + NCOL / 4;
#pragma unroll
    for (int j = 0; j < NV4; j++) {
        float4 v0, v1;
        float p0;
        p0 = MUC * rcp_fast(fmaf(r, xq[j * 4 + 0], 1.0f)); v0.x = p0; v1.x = MUC - p0;
        p0 = MUC * rcp_fast(fmaf(r, xq[j * 4 + 1], 1.0f)); v0.y = p0; v1.y = MUC - p0;
        p0 = MUC * rcp_fast(fmaf(r, xq[j * 4 + 2], 1.0f)); v0.z = p0; v1.z = MUC - p0;
        p0 = MUC * rcp_fast(fmaf(r, xq[j * 4 + 3], 1.0f)); v0.w = p0; v1.w = MUC - p0;
        stcs_f4(&o0[j * TPB + t], v0);
        stcs_f4(&o1[j * TPB + t], v1);
    }
}

extern "C" void kernel_launch(void* const* d_in, const int* in_sizes, int n_in,
                              void* d_out, int out_size) {
    const float* scores = (const float*)d_in[0];
    float* out = (float*)d_out;
    fused_kernel<<<BATCH, TPB>>>(scores, out);
}

// round 10
// speedup vs baseline: 13.2125x; 1.0531x over previous
#include <cuda_runtime.h>

#define BATCH 512
#define NCOL 4096
#define TPB 256
#define EPB 16            // elements per thread (4 float4)
#define NV4 4             // float4 chunks per thread
#define EPSI 0.1f
#define KTOP 256.0f
#define MUC (1.0f / 4096.0f)
#define MAX_HALLEY 24
#define NGROUP 16
#define GBLK 32           // blocks per group (NGROUP*GBLK == BATCH)

struct __align__(128) PadU { unsigned v; unsigned pad[31]; };

__device__ PadU g_gmax[NGROUP];    // per-group float-bits max (monotone, replay-idempotent)
__device__ PadU g_gcount[NGROUP];  // per-group arrival counters (monotone)
__device__ PadU g_rootmax;         // global float-bits max
__device__ PadU g_rootcount;       // group-last arrivals
__device__ PadU g_release;         // generation release counter

__device__ __forceinline__ float rcp_fast(float x) {
    float r;
    asm("rcp.approx.f32 %0, %1;" : "=f"(r) : "f"(x));
    return r;
}

__device__ __forceinline__ unsigned ldcg_u(const unsigned* p) {
    unsigned v;
    asm volatile("ld.global.cg.u32 %0, [%1];" : "=r"(v) : "l"(p));
    return v;
}

__device__ __forceinline__ void stcs_f4(float4* p, float4 v) {
    asm volatile("st.global.cs.v4.f32 [%0], {%1,%2,%3,%4};"
                 :: "l"(p), "f"(v.x), "f"(v.y), "f"(v.z), "f"(v.w));
}

__global__ __launch_bounds__(TPB, 4)
void fused_kernel(const float* __restrict__ s, float* __restrict__ out) {
    const int b = blockIdx.x;
    const int t = threadIdx.x;
    const int lane = t & 31, w = t >> 5;
    const int g = b >> 5;             // group id (32 blocks per group)

    __shared__ float smax[8];
    __shared__ float3 p3[2][8];

    // ---- vectorized row load ----
    const float4* __restrict__ row4 = (const float4*)(s + (size_t)b * NCOL);
    float xq[EPB];
    float m = 0.0f;
#pragma unroll
    for (int j = 0; j < NV4; j++) {
        float4 v = row4[j * TPB + t];
        xq[j * 4 + 0] = v.x; xq[j * 4 + 1] = v.y;
        xq[j * 4 + 2] = v.z; xq[j * 4 + 3] = v.w;
    }
#pragma unroll
    for (int e = 0; e < EPB; e++) {
        float x = xq[e], x1 = x - 1.0f;
        m = fmaxf(m, fmaxf(x * x, x1 * x1));
    }
#pragma unroll
    for (int o = 16; o; o >>= 1)
        m = fmaxf(m, __shfl_xor_sync(0xffffffffu, m, o));
    if (lane == 0) smax[w] = m;
    __syncthreads();

    // ---- hierarchical max + grid barrier (16 groups x 32 blocks) ----
    if (t == 0) {
        float bm = smax[0];
#pragma unroll
        for (int i = 1; i < 8; i++) bm = fmaxf(bm, smax[i]);
        // values >= 0: unsigned compare on float bits is monotone
        atomicMax(&g_gmax[g].v, __float_as_uint(bm));
        __threadfence();                                 // max visible before count
        unsigned tk = atomicAdd(&g_gcount[g].v, 1u);
        unsigned gen = tk >> 5;                          // replay generation
        if ((tk & 31u) == 31u) {
            // last block of this group this generation: escalate to root
            unsigned gm = ldcg_u(&g_gmax[g].v);
            atomicMax(&g_rootmax.v, gm);
            __threadfence();
            unsigned rt = atomicAdd(&g_rootcount.v, 1u);
            if ((rt & (NGROUP - 1u)) == NGROUP - 1u)
                atomicAdd(&g_release.v, 1u);             // last group releases all
        }
        while (ldcg_u(&g_release.v) < gen + 1u) __nanosleep(20);
        __threadfence();                                 // acquire
    }
    __syncthreads();

    const float Cmax = __uint_as_float(ldcg_u(&g_rootmax.v));
    const float ainv = rcp_fast(Cmax * EPSI);            // 1/(Cmax*eps)

    // ---- q[n] = G1/G0 = exp((2x-1)*ainv), in place ----
#pragma unroll
    for (int e = 0; e < EPB; e++)
        xq[e] = __expf((2.0f * xq[e] - 1.0f) * ainv);

    // ---- safeguarded Halley on  h(theta) = sum 1/(1+e^theta*q) - K = 0 ----
    // initial guess: soft threshold near x_c = Phi^-1(K/N) => theta0 = 4.068*ainv
    float r = __expf(4.068f * ainv);
    int buf = 0;
    for (int it = 0; it < MAX_HALLEY; ++it) {
        float A = 0.0f, A2 = 0.0f, A3 = 0.0f;
#pragma unroll
        for (int e = 0; e < EPB; e++) {
            float rc = rcp_fast(fmaf(r, xq[e], 1.0f));
            float rc2 = rc * rc;
            A += rc;
            A2 += rc2;
            A3 = fmaf(rc2, rc, A3);
        }
#pragma unroll
        for (int o = 16; o; o >>= 1) {
            A  += __shfl_xor_sync(0xffffffffu, A, o);
            A2 += __shfl_xor_sync(0xffffffffu, A2, o);
            A3 += __shfl_xor_sync(0xffffffffu, A3, o);
        }
        if (lane == 0) p3[buf][w] = make_float3(A, A2, A3);
        __syncthreads();
        float sA = 0.0f, sA2 = 0.0f, sA3 = 0.0f;
#pragma unroll
        for (int i = 0; i < 8; i++) {
            sA += p3[buf][i].x; sA2 += p3[buf][i].y; sA3 += p3[buf][i].z;
        }
        buf ^= 1;

        // h = A-K, h' = -(A-A2), h'' = A-3A2+2A3   (theta = ln r)
        float h  = sA - KTOP;
        float h1 = -(sA - sA2);
        float h2 = sA - 3.0f * sA2 + 2.0f * sA3;
        float stepN = -h * rcp_fast(fminf(h1, -1e-30f));
        float denH  = fmaf(-0.5f * h, h2, h1 * h1);
        float stepH = -h * h1 * rcp_fast(denH);
        float step = (denH > 1e-30f) ? stepH : stepN;
        if (!(step == step)) step = stepN;               // NaN guard
        step = fminf(fmaxf(step, -4.0f), 4.0f);
        r *= __expf(step);                               // uniform across block
        if (fabsf(step) < 1e-6f) break;                  // uniform branch
    }

    // ---- output: P0 = MUC/(1+r*q), P1 = MUC - P0, vector streaming stores ----
    float4* __restrict__ o0 = (float4*)(out + (size_t)b * 2 * NCOL);
    float4* __restrict__ o1 = o0 + NCOL / 4;
#pragma unroll
    for (int j = 0; j < NV4; j++) {
        float4 v0, v1;
        float p0;
        p0 = MUC * rcp_fast(fmaf(r, xq[j * 4 + 0], 1.0f)); v0.x = p0; v1.x = MUC - p0;
        p0 = MUC * rcp_fast(fmaf(r, xq[j * 4 + 1], 1.0f)); v0.y = p0; v1.y = MUC - p0;
        p0 = MUC * rcp_fast(fmaf(r, xq[j * 4 + 2], 1.0f)); v0.z = p0; v1.z = MUC - p0;
        p0 = MUC * rcp_fast(fmaf(r, xq[j * 4 + 3], 1.0f)); v0.w = p0; v1.w = MUC - p0;
        stcs_f4(&o0[j * TPB + t], v0);
        stcs_f4(&o1[j * TPB + t], v1);
    }
}

extern "C" void kernel_launch(void* const* d_in, const int* in_sizes, int n_in,
                              void* d_out, int out_size) {
    const float* scores = (const float*)d_in[0];
    float* out = (float*)d_out;
    fused_kernel<<<BATCH, TPB>>>(scores, out);
}